// round 1
// baseline (speedup 1.0000x reference)
#include <cuda_runtime.h>

#define NT 4000
#define NS 16
#define NR 512
#define NCOL (NS * NR)     // 8192 columns
#define NCOL4 (NCOL / 4)   // 2048 float4 columns
#define CHUNK 200
#define NCHUNK (NT / CHUNK) // 20

// Static device scratch (no allocation allowed).
__device__ float  g_pmax[2][NCHUNK][NCOL];
__device__ int    g_pidx[2][NCHUNK][NCOL];
__device__ double g_accum;

__global__ void tt_zero() { g_accum = 0.0; }

// Stage 1: per-(input, time-chunk, column) partial argmax of v^2.
// grid = (NCOL4/256, NCHUNK, 2), block = 256.
// Thread handles 4 adjacent columns via float4; loads are fully coalesced
// (each t-row of one input is a contiguous 32KB span).
__global__ void __launch_bounds__(256) tt_stage1(const float* __restrict__ x,
                                                 const float* __restrict__ y) {
    const int c4    = blockIdx.x * blockDim.x + threadIdx.x;  // 0..2047
    const int chunk = blockIdx.y;
    const int inp   = blockIdx.z;
    const float* v  = inp ? y : x;

    const float4* p = reinterpret_cast<const float4*>(v)
                      + (size_t)chunk * CHUNK * NCOL4 + c4;

    float m0 = -1.0f, m1 = -1.0f, m2 = -1.0f, m3 = -1.0f;
    int   i0 = 0, i1 = 0, i2 = 0, i3 = 0;
    const int tbase = chunk * CHUNK;

    // 8-deep unroll: 8 independent LDG.128 in flight per thread.
    for (int t = 0; t < CHUNK; t += 8) {
        float4 a[8];
#pragma unroll
        for (int u = 0; u < 8; u++)
            a[u] = p[(size_t)(t + u) * NCOL4];
#pragma unroll
        for (int u = 0; u < 8; u++) {
            const int ti = tbase + t + u;
            const float e0 = a[u].x * a[u].x;
            const float e1 = a[u].y * a[u].y;
            const float e2 = a[u].z * a[u].z;
            const float e3 = a[u].w * a[u].w;
            if (e0 > m0) { m0 = e0; i0 = ti; }   // strict > : first occurrence wins
            if (e1 > m1) { m1 = e1; i1 = ti; }
            if (e2 > m2) { m2 = e2; i2 = ti; }
            if (e3 > m3) { m3 = e3; i3 = ti; }
        }
    }

    float4* pm = reinterpret_cast<float4*>(&g_pmax[inp][chunk][0]);
    int4*   pi = reinterpret_cast<int4*>(&g_pidx[inp][chunk][0]);
    pm[c4] = make_float4(m0, m1, m2, m3);
    pi[c4] = make_int4(i0, i1, i2, i3);
}

// Stage 2: reduce the NCHUNK partials per column for both inputs, form
// (tx - ty)^2, block-reduce in double, atomicAdd into g_accum.
// grid = NCOL/256, block = 256.
__global__ void __launch_bounds__(256) tt_stage2() {
    const int col = blockIdx.x * blockDim.x + threadIdx.x;  // 0..8191

    float bmx = -2.0f; int bix = 0;
    float bmy = -2.0f; int biy = 0;
#pragma unroll
    for (int c = 0; c < NCHUNK; c++) {
        const float mx = g_pmax[0][c][col];
        if (mx > bmx) { bmx = mx; bix = g_pidx[0][c][col]; }  // ascending chunks:
        const float my = g_pmax[1][c][col];                   // strict > keeps earliest t
        if (my > bmy) { bmy = my; biy = g_pidx[1][c][col]; }
    }

    const float d  = (float)bix - (float)biy;   // exact: |d| < 4000
    const double sq = (double)d * (double)d;    // exact

    __shared__ double sh[256];
    sh[threadIdx.x] = sq;
    __syncthreads();
#pragma unroll
    for (int s = 128; s > 0; s >>= 1) {
        if (threadIdx.x < s) sh[threadIdx.x] += sh[threadIdx.x + s];
        __syncthreads();
    }
    if (threadIdx.x == 0)
        atomicAdd(&g_accum, sh[0]);
}

__global__ void tt_finalize(float* out) {
    out[0] = (float)(g_accum * (1.0 / (double)NCOL));
}

extern "C" void kernel_launch(void* const* d_in, const int* in_sizes, int n_in,
                              void* d_out, int out_size) {
    const float* x = (const float*)d_in[0];
    const float* y = (const float*)d_in[1];
    float* out = (float*)d_out;

    tt_zero<<<1, 1>>>();

    dim3 grid1(NCOL4 / 256, NCHUNK, 2);
    tt_stage1<<<grid1, 256>>>(x, y);

    tt_stage2<<<NCOL / 256, 256>>>();

    tt_finalize<<<1, 1>>>(out);
}

// round 2
// speedup vs baseline: 1.0022x; 1.0022x over previous
#include <cuda_runtime.h>

#define NT 4000
#define NS 16
#define NR 512
#define NCOL (NS * NR)      // 8192 columns
#define NCOL4 (NCOL / 4)    // 2048 float4 columns
#define CHUNK 200
#define NCHUNK (NT / CHUNK) // 20
#define S2_BLOCKS (NCOL / 256) // 32

// Static device scratch (no allocation allowed).
__device__ float    g_pmax[2][NCHUNK][NCOL];
__device__ int      g_pidx[2][NCHUNK][NCOL];
__device__ double   g_bsum[S2_BLOCKS];
__device__ unsigned g_done = 0;   // reset by the elected last block each run

// Stage 1: per-(input, time-chunk, column) partial argmax of v^2.
// grid = (NCOL4/256, NCHUNK, 2), block = 256. Fully coalesced float4 rows.
__global__ void __launch_bounds__(256) tt_stage1(const float* __restrict__ x,
                                                 const float* __restrict__ y) {
    const int c4    = blockIdx.x * blockDim.x + threadIdx.x;  // 0..2047
    const int chunk = blockIdx.y;
    const int inp   = blockIdx.z;
    const float* v  = inp ? y : x;

    const float4* p = reinterpret_cast<const float4*>(v)
                      + (size_t)chunk * CHUNK * NCOL4 + c4;

    float m0 = -1.0f, m1 = -1.0f, m2 = -1.0f, m3 = -1.0f;
    int   i0 = 0, i1 = 0, i2 = 0, i3 = 0;
    const int tbase = chunk * CHUNK;

    // 8 independent LDG.128 in flight per thread.
    for (int t = 0; t < CHUNK; t += 8) {
        float4 a[8];
#pragma unroll
        for (int u = 0; u < 8; u++)
            a[u] = p[(size_t)(t + u) * NCOL4];
#pragma unroll
        for (int u = 0; u < 8; u++) {
            const int ti = tbase + t + u;
            const float e0 = a[u].x * a[u].x;
            const float e1 = a[u].y * a[u].y;
            const float e2 = a[u].z * a[u].z;
            const float e3 = a[u].w * a[u].w;
            if (e0 > m0) { m0 = e0; i0 = ti; }   // strict > : first occurrence wins
            if (e1 > m1) { m1 = e1; i1 = ti; }
            if (e2 > m2) { m2 = e2; i2 = ti; }
            if (e3 > m3) { m3 = e3; i3 = ti; }
        }
    }

    float4* pm = reinterpret_cast<float4*>(&g_pmax[inp][chunk][0]);
    int4*   pi = reinterpret_cast<int4*>(&g_pidx[inp][chunk][0]);
    pm[c4] = make_float4(m0, m1, m2, m3);
    pi[c4] = make_int4(i0, i1, i2, i3);
}

// Stage 2 (fused finalize): reduce NCHUNK partials per column for both inputs,
// form (tx - ty)^2, block-reduce in double; the last-arriving block sums the
// 32 block sums and writes the mean. grid = S2_BLOCKS, block = 256.
__global__ void __launch_bounds__(256) tt_stage2(float* __restrict__ out) {
    const int col = blockIdx.x * blockDim.x + threadIdx.x;  // 0..8191

    float bmx = -2.0f; int bix = 0;
    float bmy = -2.0f; int biy = 0;
#pragma unroll
    for (int c = 0; c < NCHUNK; c++) {
        const float mx = g_pmax[0][c][col];
        if (mx > bmx) { bmx = mx; bix = g_pidx[0][c][col]; }  // ascending chunks:
        const float my = g_pmax[1][c][col];                   // strict > keeps earliest t
        if (my > bmy) { bmy = my; biy = g_pidx[1][c][col]; }
    }

    const float  d  = (float)bix - (float)biy;   // exact: |d| < 4000
    const double sq = (double)d * (double)d;     // exact

    __shared__ double sh[256];
    __shared__ bool   is_last;
    sh[threadIdx.x] = sq;
    __syncthreads();
#pragma unroll
    for (int s = 128; s > 0; s >>= 1) {
        if (threadIdx.x < s) sh[threadIdx.x] += sh[threadIdx.x + s];
        __syncthreads();
    }

    if (threadIdx.x == 0) {
        g_bsum[blockIdx.x] = sh[0];
        __threadfence();                                  // publish before ticket
        unsigned t = atomicAdd(&g_done, 1u);
        is_last = (t == S2_BLOCKS - 1);
    }
    __syncthreads();

    if (is_last && threadIdx.x < 32) {
        double s = (threadIdx.x < S2_BLOCKS) ? g_bsum[threadIdx.x] : 0.0;
#pragma unroll
        for (int o = 16; o > 0; o >>= 1)
            s += __shfl_down_sync(0xFFFFFFFFu, s, o);
        if (threadIdx.x == 0) {
            out[0] = (float)(s * (1.0 / (double)NCOL));
            g_done = 0;                                   // re-arm for next replay
        }
    }
}

extern "C" void kernel_launch(void* const* d_in, const int* in_sizes, int n_in,
                              void* d_out, int out_size) {
    const float* x = (const float*)d_in[0];
    const float* y = (const float*)d_in[1];
    float* out = (float*)d_out;

    dim3 grid1(NCOL4 / 256, NCHUNK, 2);
    tt_stage1<<<grid1, 256>>>(x, y);
    tt_stage2<<<S2_BLOCKS, 256>>>(out);
}

// round 4
// speedup vs baseline: 1.0050x; 1.0028x over previous
#include <cuda_runtime.h>

#define NT 4000
#define NS 16
#define NR 512
#define NCOL (NS * NR)      // 8192 columns
#define NCOL4 (NCOL / 4)    // 2048 float4 columns
#define CHUNK 200
#define NCHUNK (NT / CHUNK) // 20
#define S2_BLOCKS (NCOL / 256) // 32

// Static device scratch (no allocation allowed).
__device__ float    g_pmax[2][NCHUNK][NCOL];
__device__ int      g_pidx[2][NCHUNK][NCOL];
__device__ double   g_bsum[S2_BLOCKS];
__device__ unsigned g_done = 0;   // re-armed by the elected last block each run

// Stage 1: per-(input, time-chunk, column) partial argmax of v^2.
// grid = (NCOL4/256, NCHUNK, 2), block = 256. Fully coalesced float4 rows;
// all 320 CTAs are co-resident, so HBM stays saturated end-to-end.
__global__ void __launch_bounds__(256) tt_stage1(const float* __restrict__ x,
                                                 const float* __restrict__ y) {
    const int c4    = blockIdx.x * blockDim.x + threadIdx.x;  // 0..2047
    const int chunk = blockIdx.y;
    const int inp   = blockIdx.z;
    const float* v  = inp ? y : x;

    const float4* p = reinterpret_cast<const float4*>(v)
                      + (size_t)chunk * CHUNK * NCOL4 + c4;

    float m0 = -1.0f, m1 = -1.0f, m2 = -1.0f, m3 = -1.0f;
    int   i0 = 0, i1 = 0, i2 = 0, i3 = 0;
    const int tbase = chunk * CHUNK;

    // 8 independent LDG.128 in flight per thread.
    for (int t = 0; t < CHUNK; t += 8) {
        float4 a[8];
#pragma unroll
        for (int u = 0; u < 8; u++)
            a[u] = p[(size_t)(t + u) * NCOL4];
#pragma unroll
        for (int u = 0; u < 8; u++) {
            const int ti = tbase + t + u;
            const float e0 = a[u].x * a[u].x;
            const float e1 = a[u].y * a[u].y;
            const float e2 = a[u].z * a[u].z;
            const float e3 = a[u].w * a[u].w;
            if (e0 > m0) { m0 = e0; i0 = ti; }   // strict > : first occurrence wins
            if (e1 > m1) { m1 = e1; i1 = ti; }
            if (e2 > m2) { m2 = e2; i2 = ti; }
            if (e3 > m3) { m3 = e3; i3 = ti; }
        }
    }

    float4* pm = reinterpret_cast<float4*>(&g_pmax[inp][chunk][0]);
    int4*   pi = reinterpret_cast<int4*>(&g_pidx[inp][chunk][0]);
    pm[c4] = make_float4(m0, m1, m2, m3);
    pi[c4] = make_int4(i0, i1, i2, i3);
}

// Stage 2 (fused finalize): reduce NCHUNK partials per column for both inputs,
// form (tx - ty)^2, block-reduce in double; the last-arriving block sums the
// 32 block sums and writes the mean. grid = S2_BLOCKS, block = 256.
__global__ void __launch_bounds__(256) tt_stage2(float* __restrict__ out) {
    const int col = blockIdx.x * blockDim.x + threadIdx.x;  // 0..8191

    float bmx = -2.0f; int bix = 0;
    float bmy = -2.0f; int biy = 0;
#pragma unroll
    for (int c = 0; c < NCHUNK; c++) {
        const float mx = g_pmax[0][c][col];
        if (mx > bmx) { bmx = mx; bix = g_pidx[0][c][col]; }  // ascending chunks:
        const float my = g_pmax[1][c][col];                   // strict > keeps earliest t
        if (my > bmy) { bmy = my; biy = g_pidx[1][c][col]; }
    }

    const float  d  = (float)bix - (float)biy;   // exact: |d| < 4000
    const double sq = (double)d * (double)d;     // exact

    __shared__ double sh[256];
    __shared__ bool   is_last;
    sh[threadIdx.x] = sq;
    __syncthreads();
#pragma unroll
    for (int s = 128; s > 0; s >>= 1) {
        if (threadIdx.x < s) sh[threadIdx.x] += sh[threadIdx.x + s];
        __syncthreads();
    }

    if (threadIdx.x == 0) {
        g_bsum[blockIdx.x] = sh[0];
        __threadfence();                                  // publish before ticket
        unsigned t = atomicAdd(&g_done, 1u);
        is_last = (t == S2_BLOCKS - 1);
    }
    __syncthreads();

    if (is_last && threadIdx.x < 32) {
        double s = (threadIdx.x < S2_BLOCKS) ? g_bsum[threadIdx.x] : 0.0;
#pragma unroll
        for (int o = 16; o > 0; o >>= 1)
            s += __shfl_down_sync(0xFFFFFFFFu, s, o);
        if (threadIdx.x == 0) {
            out[0] = (float)(s * (1.0 / (double)NCOL));
            g_done = 0;                                   // re-arm for next replay
        }
    }
}

extern "C" void kernel_launch(void* const* d_in, const int* in_sizes, int n_in,
                              void* d_out, int out_size) {
    const float* x = (const float*)d_in[0];
    const float* y = (const float*)d_in[1];
    float* out = (float*)d_out;

    dim3 grid1(NCOL4 / 256, NCHUNK, 2);
    tt_stage1<<<grid1, 256>>>(x, y);
    tt_stage2<<<S2_BLOCKS, 256>>>(out);
}